// round 1
// baseline (speedup 1.0000x reference)
#include <cuda_runtime.h>
#include <cuda_pipeline.h>

#define H       256
#define HK4     64        // H / 4
#define NMAX    131072
#define PPH     16
#define KOCC    8
#define KSUBJ   16
#define OCC     128       // total occurrence classes
#define NLOG    40        // 16 phase + 8 occ + 16 subj logits per row
#define TM      64        // rows per tile
#define THREADS 256
#define SPLIT   8         // CTAs per occurrence bucket
#define XSTRIDE 65        // float4 units per X row in smem (64 + 1 pad)
#define WSTRIDE 65        // float4 units per weight row in smem
#define LSTRIDE 41        // floats per logit row in smem (40 + 1 pad, odd)

// ---- scratch (device globals; no allocation allowed) ----
__device__ int g_hist[OCC];
__device__ int g_off[OCC + 1];
__device__ int g_cursor[OCC];
__device__ int g_occid[NMAX];
__device__ int g_perm[NMAX];

// ---------------- binning pre-pass ----------------
__global__ void k_zero() { g_hist[threadIdx.x] = 0; }

__global__ void k_hist(const int* __restrict__ xph, const int* __restrict__ xol, int n) {
    __shared__ int sh[OCC];
    int tid = threadIdx.x;
    if (tid < OCC) sh[tid] = 0;
    __syncthreads();
    for (int i = blockIdx.x * blockDim.x + tid; i < n; i += gridDim.x * blockDim.x) {
        int occ = xph[i] * KOCC + xol[i];
        g_occid[i] = occ;
        atomicAdd(&sh[occ], 1);
    }
    __syncthreads();
    if (tid < OCC) atomicAdd(&g_hist[tid], sh[tid]);
}

__global__ void k_scan() {
    // single thread: 128 elements, trivial
    int s = 0;
    for (int j = 0; j < OCC; j++) {
        g_off[j] = s;
        g_cursor[j] = s;
        s += g_hist[j];
    }
    g_off[OCC] = s;
}

__global__ void k_scatter(int n) {
    for (int i = blockIdx.x * blockDim.x + threadIdx.x; i < n; i += gridDim.x * blockDim.x) {
        int occ = g_occid[i];
        int pos = atomicAdd(&g_cursor[occ], 1);
        g_perm[pos] = i;
    }
}

// ---------------- main compute ----------------
// One CTA handles a slice of one occurrence bucket. Weights for that bucket
// (16 phase rows + 8 occ rows + 16 subj rows = 40 x 256 fp32) live in SMEM.
// X rows are gathered via g_perm in 64-row tiles (cp.async double buffered),
// 64x40x256 fp32 GEMM per tile (thread tile 2 rows x 5 logits), then a
// per-row softmax epilogue from SMEM.
extern __shared__ float4 smem4[];

__global__ void __launch_bounds__(THREADS, 1)
k_main(const float* __restrict__ X,
       const float* __restrict__ Wph, const float* __restrict__ bph,
       const float* __restrict__ Wpo, const float* __restrict__ bpo,
       const float* __restrict__ Wos, const float* __restrict__ bos,
       const int* __restrict__ xsl,
       float* __restrict__ out, int n)
{
    const int o  = blockIdx.x;      // occurrence class 0..127
    const int f  = o >> 3;          // phase
    const int ol = o & 7;           // local occurrence
    const int bstart = g_off[o], bend = g_off[o + 1];
    const int cnt   = bend - bstart;
    const int chunk = (cnt + SPLIT - 1) / SPLIT;
    const int start = bstart + (int)blockIdx.y * chunk;
    const int end   = min(start + chunk, bend);
    if (start >= end) return;       // uniform across CTA

    const int tid = threadIdx.x;

    float4* sX = smem4;                                   // 2 * TM * XSTRIDE f4
    float4* sW = smem4 + 2 * TM * XSTRIDE;                // NLOG * WSTRIDE f4
    float*  fb = (float*)(sW + NLOG * WSTRIDE);
    float*  sL = fb;                                      // TM * LSTRIDE floats
    float*  sB = fb + TM * LSTRIDE;                       // NLOG floats

    // ---- load this bucket's weights into SMEM (amortized over all tiles) ----
    for (int idx = tid; idx < NLOG * HK4; idx += THREADS) {
        int j = idx >> 6, k4 = idx & 63;
        const float* src;
        if (j < 16)      src = Wph + (size_t)j * H;
        else if (j < 24) src = Wpo + (size_t)(f * KOCC + j - 16) * H;
        else             src = Wos + (size_t)(o * KSUBJ + j - 24) * H;
        sW[j * WSTRIDE + k4] = ((const float4*)src)[k4];
    }
    if (tid < NLOG) {
        float b;
        if (tid < 16)      b = bph[tid];
        else if (tid < 24) b = bpo[f * KOCC + tid - 16];
        else               b = bos[o * KSUBJ + tid - 24];
        sB[tid] = b;
    }

    const int nrows  = end - start;
    const int ntiles = (nrows + TM - 1) / TM;

    auto loadTile = [&](int t, int b) {
        int rowbase = start + t * TM;
        float4* dst = sX + b * TM * XSTRIDE;
        #pragma unroll
        for (int i = 0; i < (TM * HK4) / THREADS; i++) {
            int idx = tid + i * THREADS;
            int r = idx >> 6, k4 = idx & 63;
            int gi = rowbase + r;
            if (gi < end) {
                int orig = g_perm[gi];
                __pipeline_memcpy_async(&dst[r * XSTRIDE + k4],
                                        X + (size_t)orig * H + k4 * 4, 16);
            }
        }
        __pipeline_commit();
    };

    loadTile(0, 0);

    // thread tile mapping: warp spans 8 logit-groups x 4 row-pairs => conflict-free LDS
    const int rp = tid >> 3;   // 0..31 : rows {2rp, 2rp+1}
    const int jg = tid & 7;    // 0..7  : logits jg*5 .. jg*5+4

    for (int t = 0; t < ntiles; t++) {
        if (t + 1 < ntiles) { loadTile(t + 1, (t + 1) & 1); __pipeline_wait_prior(1); }
        else                { __pipeline_wait_prior(0); }
        __syncthreads();    // S1: tile t ready; sL free (prev epilogue done)

        const float4* xb  = sX + (t & 1) * TM * XSTRIDE;
        const float4* x0p = xb + (2 * rp)     * XSTRIDE;
        const float4* x1p = xb + (2 * rp + 1) * XSTRIDE;
        const float4* wbase = sW + (jg * 5) * WSTRIDE;

        float acc[2][5];
        #pragma unroll
        for (int r2 = 0; r2 < 2; r2++)
            #pragma unroll
            for (int j = 0; j < 5; j++) acc[r2][j] = 0.f;

        #pragma unroll 4
        for (int k4 = 0; k4 < HK4; k4++) {
            float4 xa = x0p[k4];
            float4 xc = x1p[k4];
            #pragma unroll
            for (int j = 0; j < 5; j++) {
                float4 w = wbase[j * WSTRIDE + k4];
                acc[0][j] += xa.x * w.x + xa.y * w.y + xa.z * w.z + xa.w * w.w;
                acc[1][j] += xc.x * w.x + xc.y * w.y + xc.z * w.z + xc.w * w.w;
            }
        }

        // stage logits (+bias) for the epilogue
        #pragma unroll
        for (int r2 = 0; r2 < 2; r2++)
            #pragma unroll
            for (int j = 0; j < 5; j++)
                sL[(2 * rp + r2) * LSTRIDE + jg * 5 + j] = acc[r2][j] + sB[jg * 5 + j];

        __syncthreads();    // S2: logits complete

        if (tid < TM) {
            int gi = start + t * TM + tid;
            if (gi < end) {
                int orig = g_perm[gi];
                const float* L = sL + tid * LSTRIDE;
                float s0 = 0.f;
                #pragma unroll
                for (int j = 0; j < 16; j++) s0 += __expf(L[j]);
                float p1 = __expf(L[f]) / s0;
                float s1 = 0.f;
                #pragma unroll
                for (int j = 16; j < 24; j++) s1 += __expf(L[j]);
                float p2 = __expf(L[16 + ol]) / s1;
                int sl = xsl[orig];
                float s2 = 0.f;
                #pragma unroll
                for (int j = 24; j < 40; j++) s2 += __expf(L[j]);
                float p3 = __expf(L[24 + sl]) / s2;
                float po = p1 * p2;
                out[orig]                   = p1;
                out[(size_t)n + orig]       = po;
                out[2 * (size_t)n + orig]   = po * p3;
            }
        }
        __syncthreads();    // S3: epilogue done before buffers are reused
    }
}

// ---------------- launch ----------------
extern "C" void kernel_launch(void* const* d_in, const int* in_sizes, int n_in,
                              void* d_out, int out_size)
{
    const float* X   = (const float*)d_in[0];
    const float* Wph = (const float*)d_in[1];
    const float* bph = (const float*)d_in[2];
    const float* Wpo = (const float*)d_in[3];
    const float* bpo = (const float*)d_in[4];
    const float* Wos = (const float*)d_in[5];
    const float* bos = (const float*)d_in[6];
    const int*   xph = (const int*)d_in[7];
    const int*   xol = (const int*)d_in[8];
    const int*   xsl = (const int*)d_in[9];
    float* out = (float*)d_out;
    const int n = in_sizes[0] / H;

    k_zero<<<1, OCC>>>();
    k_hist<<<256, 256>>>(xph, xol, n);
    k_scan<<<1, 1>>>();
    k_scatter<<<256, 256>>>(n);

    size_t smem = (size_t)(2 * TM * XSTRIDE + NLOG * WSTRIDE) * sizeof(float4)
                + (size_t)(TM * LSTRIDE + NLOG) * sizeof(float);
    cudaFuncSetAttribute(k_main, cudaFuncAttributeMaxDynamicSharedMemorySize, (int)smem);
    dim3 grid(OCC, SPLIT);
    k_main<<<grid, THREADS, smem>>>(X, Wph, bph, Wpo, bpo, Wos, bos, xsl, out, n);
}

// round 4
// speedup vs baseline: 1.9064x; 1.9064x over previous
#include <cuda_runtime.h>
#include <cuda_pipeline.h>

#define H       256
#define HK4     64
#define NMAX    131072
#define KOCC    8
#define KSUBJ   16
#define OCC     128
#define NLOG    40
#define TM      128       // rows per tile (one tile per CTA)
#define CH4     32        // float4 per row per K-chunk (K split in halves)
#define THREADS 256
#define NBLK    128       // prepass blocks
#define MAXT    16        // max tiles per bucket (cnt up to 2048 >> 30 sigma)
#define XST     33        // f4 stride per row in chunk buffer (32 + 1 pad)
#define WST     65        // f4 stride per weight row (64 + 1 pad)
#define LST     41        // float stride per logit row

#define FMA2(acc, a, b) asm("fma.rn.f32x2 %0, %1, %2, %0;" : "+l"(acc) : "l"(a), "l"(b))

// ---- scratch (device globals; no allocation allowed) ----
__device__ int g_bhist[NBLK][OCC];
__device__ int g_bbase[NBLK][OCC];
__device__ int g_occid[NMAX];
__device__ int g_off[OCC];          // tile-padded bucket start
__device__ int g_cnt[OCC];          // actual bucket count
__device__ int g_perm[NMAX + OCC * TM];

// ================= prepass (no global atomics) =================
__global__ void k_hist(const int* __restrict__ xph, const int* __restrict__ xol, int n) {
    __shared__ int sh[OCC];
    int b = blockIdx.x, tid = threadIdx.x;
    if (tid < OCC) sh[tid] = 0;
    __syncthreads();
    int per = (n + NBLK - 1) / NBLK;
    int s0 = b * per, s1 = min(s0 + per, n);
    for (int i = s0 + tid; i < s1; i += THREADS) {
        int occ = xph[i] * KOCC + xol[i];
        g_occid[i] = occ;
        atomicAdd(&sh[occ], 1);
    }
    __syncthreads();
    if (tid < OCC) g_bhist[b][tid] = sh[tid];
}

__global__ void k_scan() {
    __shared__ int tot[OCC];
    int o = threadIdx.x;            // 128 threads
    int s = 0;
    for (int b = 0; b < NBLK; b++) s += g_bhist[b][o];
    tot[o] = s;
    __syncthreads();
    if (o == 0) {
        int run = 0;
        for (int j = 0; j < OCC; j++) {
            g_off[j] = run;
            g_cnt[j] = tot[j];
            run += ((tot[j] + TM - 1) / TM) * TM;   // tile-aligned padding
        }
    }
    __syncthreads();
    int run2 = g_off[o];
    for (int b = 0; b < NBLK; b++) { g_bbase[b][o] = run2; run2 += g_bhist[b][o]; }
}

__global__ void k_scatter(int n) {
    __shared__ int cur[OCC];
    int b = blockIdx.x, tid = threadIdx.x;
    if (tid < OCC) cur[tid] = g_bbase[b][tid];
    __syncthreads();
    int per = (n + NBLK - 1) / NBLK;
    int s0 = b * per, s1 = min(s0 + per, n);
    for (int i = s0 + tid; i < s1; i += THREADS) {
        int occ = g_occid[i];
        int pos = atomicAdd(&cur[occ], 1);   // smem atomic only
        g_perm[pos] = i;
    }
}

// ================= main compute =================
// One CTA = one 128-row tile of one occurrence bucket.
// Weights (40x256 fp32) in SMEM; X gathered in two K-half chunks
// (cp.async double buffered); f32x2-packed FFMA GEMM, thread tile
// 4 rows (stride 32) x 5 logits; softmax epilogue from SMEM.
extern __shared__ float4 smem4[];

__global__ void __launch_bounds__(THREADS, 1)
k_main(const float* __restrict__ X,
       const float* __restrict__ Wph, const float* __restrict__ bph,
       const float* __restrict__ Wpo, const float* __restrict__ bpo,
       const float* __restrict__ Wos, const float* __restrict__ bos,
       const int* __restrict__ xsl,
       float* __restrict__ out, int n)
{
    const int o  = blockIdx.x;
    const int f  = o >> 3;
    const int ol = o & 7;
    const int cnt = g_cnt[o];
    const int t0  = (int)blockIdx.y * TM;
    if (t0 >= cnt) return;
    const int start = g_off[o] + t0;
    const int rows  = min(TM, cnt - t0);
    const int tid = threadIdx.x;

    float4* sX = smem4;                             // 2 * TM * XST f4
    float4* sW = smem4 + 2 * TM * XST;              // NLOG * WST f4
    float*  sL = (float*)(sW + NLOG * WST);         // TM * LST floats
    float*  sB = sL + TM * LST;                     // 64 floats (40 used)
    int*    sP = (int*)(sB + 64);                   // TM ints

    // weights -> smem via cp.async (group 0)
    for (int idx = tid; idx < NLOG * HK4; idx += THREADS) {
        int j = idx >> 6, k4 = idx & 63;
        const float4* src;
        if (j < 16)      src = (const float4*)(Wph + (size_t)j * H);
        else if (j < 24) src = (const float4*)(Wpo + (size_t)(f * KOCC + j - 16) * H);
        else             src = (const float4*)(Wos + (size_t)(o * KSUBJ + j - 24) * H);
        __pipeline_memcpy_async(&sW[j * WST + k4], src + k4, 16);
    }
    __pipeline_commit();

    if (tid < TM) sP[tid] = (tid < rows) ? g_perm[start + tid] : 0;
    if (tid < NLOG) {
        float b;
        if (tid < 16)      b = bph[tid];
        else if (tid < 24) b = bpo[f * KOCC + tid - 16];
        else               b = bos[o * KSUBJ + tid - 24];
        sB[tid] = b;
    }
    __syncthreads();   // sP ready for the gather below

    // issue both K-half chunks (groups 1, 2)
    #pragma unroll
    for (int h = 0; h < 2; h++) {
        float4* dst = sX + h * TM * XST;
        #pragma unroll
        for (int i = 0; i < (TM * CH4) / THREADS; i++) {
            int idx = tid + i * THREADS;
            int r = idx >> 5, k4 = idx & 31;
            if (r < rows)
                __pipeline_memcpy_async(&dst[r * XST + k4],
                                        X + (size_t)sP[r] * H + (h * CH4 + k4) * 4, 16);
        }
        __pipeline_commit();
    }

    const int rowg = tid >> 3;   // 0..31 : rows rowg + 32*i
    const int jg   = tid & 7;    // 0..7  : logits jg*5 .. jg*5+4

    unsigned long long acc[4][5];
    #pragma unroll
    for (int i = 0; i < 4; i++)
        #pragma unroll
        for (int j = 0; j < 5; j++) acc[i][j] = 0ull;

    __pipeline_wait_prior(1);    // weights + chunk 0
    __syncthreads();

    #pragma unroll
    for (int h = 0; h < 2; h++) {
        const ulonglong2* xb = (const ulonglong2*)(sX + h * TM * XST);
        // BUGFIX (R2->R3): weights must advance through K with the X chunk.
        const ulonglong2* wb = ((const ulonglong2*)sW) + (jg * 5) * WST + h * CH4;
        #pragma unroll 4
        for (int k4 = 0; k4 < CH4; k4++) {
            ulonglong2 xv[4];
            #pragma unroll
            for (int i = 0; i < 4; i++) xv[i] = xb[(rowg + 32 * i) * XST + k4];
            #pragma unroll
            for (int j = 0; j < 5; j++) {
                ulonglong2 wv = wb[j * WST + k4];
                #pragma unroll
                for (int i = 0; i < 4; i++) {
                    FMA2(acc[i][j], xv[i].x, wv.x);
                    FMA2(acc[i][j], xv[i].y, wv.y);
                }
            }
        }
        if (h == 0) { __pipeline_wait_prior(0); __syncthreads(); }  // chunk 1 ready
    }

    // stage logits
    #pragma unroll
    for (int i = 0; i < 4; i++)
        #pragma unroll
        for (int j = 0; j < 5; j++) {
            unsigned int lo, hi;
            asm("mov.b64 {%0,%1}, %2;" : "=r"(lo), "=r"(hi) : "l"(acc[i][j]));
            sL[(rowg + 32 * i) * LST + jg * 5 + j] =
                __uint_as_float(lo) + __uint_as_float(hi);
        }
    __syncthreads();

    if (tid < rows) {
        int orig = sP[tid];
        int sl = xsl[orig];
        const float* L = sL + tid * LST;
        float s0 = 0.f;
        #pragma unroll
        for (int j = 0; j < 16; j++) s0 += __expf(L[j] + sB[j]);
        float p1 = __expf(L[f] + sB[f]) / s0;
        float s1 = 0.f;
        #pragma unroll
        for (int j = 16; j < 24; j++) s1 += __expf(L[j] + sB[j]);
        float p2 = __expf(L[16 + ol] + sB[16 + ol]) / s1;
        float s2 = 0.f;
        #pragma unroll
        for (int j = 24; j < 40; j++) s2 += __expf(L[j] + sB[j]);
        float p3 = __expf(L[24 + sl] + sB[24 + sl]) / s2;
        float po = p1 * p2;
        out[orig]                 = p1;
        out[(size_t)n + orig]     = po;
        out[2 * (size_t)n + orig] = po * p3;
    }
}

// ================= launch =================
extern "C" void kernel_launch(void* const* d_in, const int* in_sizes, int n_in,
                              void* d_out, int out_size)
{
    const float* X   = (const float*)d_in[0];
    const float* Wph = (const float*)d_in[1];
    const float* bph = (const float*)d_in[2];
    const float* Wpo = (const float*)d_in[3];
    const float* bpo = (const float*)d_in[4];
    const float* Wos = (const float*)d_in[5];
    const float* bos = (const float*)d_in[6];
    const int*   xph = (const int*)d_in[7];
    const int*   xol = (const int*)d_in[8];
    const int*   xsl = (const int*)d_in[9];
    float* out = (float*)d_out;
    const int n = in_sizes[0] / H;

    k_hist<<<NBLK, THREADS>>>(xph, xol, n);
    k_scan<<<1, OCC>>>();
    k_scatter<<<NBLK, THREADS>>>(n);

    size_t smem = (size_t)(2 * TM * XST + NLOG * WST) * sizeof(float4)
                + (size_t)(TM * LST + 64) * sizeof(float)
                + (size_t)TM * sizeof(int);
    cudaFuncSetAttribute(k_main, cudaFuncAttributeMaxDynamicSharedMemorySize, (int)smem);
    dim3 grid(OCC, MAXT);
    k_main<<<grid, THREADS, smem>>>(X, Wph, bph, Wpo, bpo, Wos, bos, xsl, out, n);
}